// round 5
// baseline (speedup 1.0000x reference)
#include <cuda_runtime.h>
#include <math.h>

#define BB   8
#define SS   1024
#define DD   1024
#define HH   16
#define DKK  64
#define DF   4096
#define NTOK (BB*SS)        // 8192 tokens

// ---------------- scratch (static device globals; no allocation) ------------
__device__ float g_xq[NTOK*DD];        // LN output (rounded+perm), both LNs
__device__ float g_xr[NTOK*DD];        // x rounded+perm
__device__ float g_q [NTOK*DD];        // perm in dk
__device__ float g_k [NTOK*DD];        // perm in dk
__device__ float g_v [NTOK*DD];        // natural
__device__ float g_ctx[NTOK*DD];       // perm in dk (feeds O-proj)
__device__ float g_x1[NTOK*DD];        // natural (residual + LN input)
__device__ float g_h [NTOK*DF];        // perm (feeds W2)
__device__ float g_w [12*1024*1024];   // rounded+perm weights

// ---------------- helpers ----------------------------------------------------
__device__ __forceinline__ unsigned f2tf(float f) {
    unsigned u;
    asm("cvt.rna.tf32.f32 %0, %1;" : "=r"(u) : "f"(f));
    return u;
}
__device__ __forceinline__ float roundtf(float f) { return __uint_as_float(f2tf(f)); }
__device__ __forceinline__ int pc16(int c) {       // sigma within 16-group (involution)
    return (c & ~15) | ((c & 3) << 2) | ((c >> 2) & 3);
}
__device__ __forceinline__ void cpa16(void* s, const float* g) {
    unsigned sa = (unsigned)__cvta_generic_to_shared(s);
    asm volatile("cp.async.cg.shared.global [%0], [%1], 16;" :: "r"(sa), "l"(g));
}
__device__ __forceinline__ void cp_commit() { asm volatile("cp.async.commit_group;"); }
template<int N> __device__ __forceinline__ void cp_wait() {
    asm volatile("cp.async.wait_group %0;" :: "n"(N));
}
__device__ __forceinline__ void mma8(float* c, const unsigned* a, const unsigned* b) {
    asm volatile(
        "mma.sync.aligned.m16n8k8.row.col.f32.tf32.tf32.f32 "
        "{%0,%1,%2,%3}, {%4,%5,%6,%7}, {%8,%9}, {%0,%1,%2,%3};"
        : "+f"(c[0]), "+f"(c[1]), "+f"(c[2]), "+f"(c[3])
        : "r"(a[0]), "r"(a[1]), "r"(a[2]), "r"(a[3]), "r"(b[0]), "r"(b[1]));
}

// ---------------- round to tf32 + permute k within 16-groups -----------------
// One thread per 16-float group: out[base + 4b + a] = round(in[base + 4a + b])
__global__ void __launch_bounds__(256)
round_perm_k(const float* __restrict__ in, float* __restrict__ out, int ngroups)
{
    int i = blockIdx.x * 256 + threadIdx.x;
    if (i >= ngroups) return;
    const float4* ip = (const float4*)(in) + (long)i * 4;
    float4 v0 = ip[0], v1 = ip[1], v2 = ip[2], v3 = ip[3];
    float4* op = (float4*)(out) + (long)i * 4;
    op[0] = make_float4(roundtf(v0.x), roundtf(v1.x), roundtf(v2.x), roundtf(v3.x));
    op[1] = make_float4(roundtf(v0.y), roundtf(v1.y), roundtf(v2.y), roundtf(v3.y));
    op[2] = make_float4(roundtf(v0.z), roundtf(v1.z), roundtf(v2.z), roundtf(v3.z));
    op[3] = make_float4(roundtf(v0.w), roundtf(v1.w), roundtf(v2.w), roundtf(v3.w));
}

// ---------------- tf32 tensor-core GEMM (5-stage cp.async) ------------------
// VEC=true: NT GEMM, operands stored k-permuted; float4 swizzled smem tiles.
// VEC=false: legacy scalar path (BT selects layout), CVTA rounds A in-loop.
// PERMN: write output columns k-permuted (for intermediates feeding later GEMMs).
// MODE: 0 bias | 1 bias+res+BN | 2 bias+GELU+BN | 3 mask-scale | 4 raw
template<int BM,int BN,int WM,int WN,bool BT,int MODE,bool CVTA,bool VEC,bool PERMN,bool RND>
__global__ void __launch_bounds__(256)
gemm_tc(const float* __restrict__ A, int lda, long aS1, long aS2,
        const float* __restrict__ B, int ldb, long bS1, long bS2,
        float*       __restrict__ C, int ldc, long cS1, long cS2,
        int K,
        const float* __restrict__ bias,
        const float* __restrict__ res,
        const float* __restrict__ bng, const float* __restrict__ bnb,
        const float* __restrict__ bnm, const float* __restrict__ bnv,
        const int*   __restrict__ mask, int maskS1)
{
    constexpr int BK  = 16;
    constexpr int ST  = 5;
    // VEC: float4 tiles [rows][4] with XOR swizzle. non-VEC: padded scalar tiles.
    constexpr int AST = BK + 4;
    constexpr int BSTs= BT ? (BK + 4) : (BN + 4);
    constexpr int ASZ = VEC ? (BM * 4)            : (BM * AST);   // units: f4 / f
    constexpr int BSZ = VEC ? (BN * 4)            : (BT ? BN * BSTs : BK * BSTs);

    extern __shared__ char smem_raw[];

    const int z  = blockIdx.z;
    const int zb = z >> 4;
    const int zh = z & 15;
    A += (long)zb * aS1 + (long)zh * aS2;
    B += (long)zb * bS1 + (long)zh * bS2;
    C += (long)zb * cS1 + (long)zh * cS2;

    const int tid = threadIdx.x;
    const int m0  = blockIdx.y * BM;
    const int n0  = blockIdx.x * BN;

    const int warp = tid >> 5, lane = tid & 31;
    constexpr int WGN = BN / WN;
    const int wm = warp / WGN, wn = warp % WGN;
    const int g  = lane >> 2,  t  = lane & 3;
    constexpr int MT  = WM / 16;
    constexpr int NTL = WN / 8;

    float c[MT][NTL][4];
    #pragma unroll
    for (int i = 0; i < MT; i++)
        #pragma unroll
        for (int j = 0; j < NTL; j++)
            #pragma unroll
            for (int e = 0; e < 4; e++) c[i][j][e] = 0.0f;

    const int iters = K / BK;

    float4* sA4 = (float4*)smem_raw;                       // VEC
    float4* sB4 = sA4 + ST * ASZ;
    float*  sAf = (float*)smem_raw;                        // non-VEC
    float*  sBf = sAf + ST * ASZ;

    auto load_stage = [&](int it, int buf) {
        const int k0 = it * BK;
        if constexpr (VEC) {
            float4* dA = sA4 + buf * ASZ;
            float4* dB = sB4 + buf * BSZ;
            #pragma unroll
            for (int s = tid; s < BM * 4; s += 256) {
                int m = s >> 2, ck = s & 3;
                cpa16(&dA[m * 4 + (ck ^ (m & 3))],
                      A + (long)(m0 + m) * lda + k0 + ck * 4);
            }
            #pragma unroll
            for (int s = tid; s < BN * 4; s += 256) {
                int n = s >> 2, ck = s & 3;
                cpa16(&dB[n * 4 + (ck ^ (n & 3))],
                      B + (long)(n0 + n) * ldb + k0 + ck * 4);
            }
        } else {
            float* dA = sAf + buf * ASZ;
            float* dB = sBf + buf * BSZ;
            #pragma unroll
            for (int s = tid; s < BM * 4; s += 256) {
                int row = s >> 2, seg = s & 3;
                cpa16(&dA[row * AST + seg * 4],
                      A + (long)(m0 + row) * lda + k0 + seg * 4);
            }
            if constexpr (BT) {
                #pragma unroll
                for (int s = tid; s < BN * 4; s += 256) {
                    int row = s >> 2, seg = s & 3;
                    cpa16(&dB[row * BSTs + seg * 4],
                          B + (long)(n0 + row) * ldb + k0 + seg * 4);
                }
            } else {
                constexpr int SPR = BN / 4;
                #pragma unroll
                for (int s = tid; s < BK * SPR; s += 256) {
                    int row = s / SPR, seg = s % SPR;
                    cpa16(&dB[row * BSTs + seg * 4],
                          B + (long)(k0 + row) * ldb + n0 + seg * 4);
                }
            }
        }
    };

    // prologue: fill ST-1 stages (commit a group per slot even if empty)
    #pragma unroll
    for (int s = 0; s < ST - 1; s++) {
        if (s < iters) load_stage(s, s);
        cp_commit();
    }

    for (int it = 0; it < iters; ++it) {
        cp_wait<ST - 2>();
        __syncthreads();

        if (it + ST - 1 < iters) load_stage(it + ST - 1, (it + ST - 1) % ST);
        cp_commit();

        const int buf = it % ST;

        if constexpr (VEC) {
            const float4* bA = sA4 + buf * ASZ;
            const float4* bB = sB4 + buf * BSZ;
            float4 va[MT][2], vb[NTL];
            #pragma unroll
            for (int mt = 0; mt < MT; mt++) {
                const int mr = wm * WM + mt * 16 + g;
                va[mt][0] = bA[(mr    ) * 4 + (t ^ (mr & 3))];
                va[mt][1] = bA[(mr + 8) * 4 + (t ^ (mr & 3))];
            }
            #pragma unroll
            for (int nt = 0; nt < NTL; nt++) {
                const int nc = wn * WN + nt * 8 + g;
                vb[nt] = bB[nc * 4 + (t ^ (nc & 3))];
            }
            #pragma unroll
            for (int half = 0; half < 2; half++) {
                unsigned a[MT][4], b[NTL][2];
                #pragma unroll
                for (int mt = 0; mt < MT; mt++) {
                    a[mt][0] = __float_as_uint(half ? va[mt][0].z : va[mt][0].x);
                    a[mt][1] = __float_as_uint(half ? va[mt][1].z : va[mt][1].x);
                    a[mt][2] = __float_as_uint(half ? va[mt][0].w : va[mt][0].y);
                    a[mt][3] = __float_as_uint(half ? va[mt][1].w : va[mt][1].y);
                }
                #pragma unroll
                for (int nt = 0; nt < NTL; nt++) {
                    b[nt][0] = __float_as_uint(half ? vb[nt].z : vb[nt].x);
                    b[nt][1] = __float_as_uint(half ? vb[nt].w : vb[nt].y);
                }
                #pragma unroll
                for (int mt = 0; mt < MT; mt++)
                    #pragma unroll
                    for (int nt = 0; nt < NTL; nt++)
                        mma8(c[mt][nt], a[mt], b[nt]);
            }
        } else {
            const float* bA = sAf + buf * ASZ;
            const float* bB = sBf + buf * BSZ;
            #pragma unroll
            for (int kb = 0; kb < BK; kb += 8) {
                unsigned a[MT][4], b[NTL][2];
                #pragma unroll
                for (int mt = 0; mt < MT; mt++) {
                    const int mr = wm * WM + mt * 16 + g;
                    float f0 = bA[(mr    ) * AST + kb + t    ];
                    float f1 = bA[(mr + 8) * AST + kb + t    ];
                    float f2 = bA[(mr    ) * AST + kb + t + 4];
                    float f3 = bA[(mr + 8) * AST + kb + t + 4];
                    if constexpr (CVTA) {
                        a[mt][0] = f2tf(f0); a[mt][1] = f2tf(f1);
                        a[mt][2] = f2tf(f2); a[mt][3] = f2tf(f3);
                    } else {
                        a[mt][0] = __float_as_uint(f0); a[mt][1] = __float_as_uint(f1);
                        a[mt][2] = __float_as_uint(f2); a[mt][3] = __float_as_uint(f3);
                    }
                }
                #pragma unroll
                for (int nt = 0; nt < NTL; nt++) {
                    const int nc = wn * WN + nt * 8 + g;
                    float f0, f1;
                    if constexpr (BT) {
                        f0 = bB[nc * BSTs + kb + t    ];
                        f1 = bB[nc * BSTs + kb + t + 4];
                    } else {
                        f0 = bB[(kb + t    ) * BSTs + nc];
                        f1 = bB[(kb + t + 4) * BSTs + nc];
                    }
                    b[nt][0] = __float_as_uint(f0);
                    b[nt][1] = __float_as_uint(f1);
                }
                #pragma unroll
                for (int mt = 0; mt < MT; mt++)
                    #pragma unroll
                    for (int nt = 0; nt < NTL; nt++)
                        mma8(c[mt][nt], a[mt], b[nt]);
            }
        }
        __syncthreads();
    }

    // ---- epilogue ----
    auto ep = [&](float v, int n, long m) -> float {
        if constexpr (MODE == 0) {
            v += bias[n];
        } else if constexpr (MODE == 1) {
            v += bias[n] + res[m * ldc + n];
            v = (v - bnm[n]) * rsqrtf(bnv[n] + 1e-5f) * bng[n] + bnb[n];
        } else if constexpr (MODE == 2) {
            v += bias[n];
            v = 0.5f * v * (1.0f + erff(v * 0.70710678118654752f));
            v = (v - bnm[n]) * rsqrtf(bnv[n] + 1e-5f) * bng[n] + bnb[n];
        } else if constexpr (MODE == 3) {
            v = (mask[(long)zb * maskS1 + n] == 0) ? -1e9f : v * 0.125f;
        }
        if constexpr (RND) v = roundtf(v);
        return v;
    };

    #pragma unroll
    for (int mt = 0; mt < MT; mt++) {
        #pragma unroll
        for (int nt = 0; nt < NTL; nt++) {
            const int row = m0 + wm * WM + mt * 16 + g;
            const int col = n0 + wn * WN + nt * 8 + 2 * t;
            float v00 = ep(c[mt][nt][0], col,     row);
            float v01 = ep(c[mt][nt][1], col + 1, row);
            float v10 = ep(c[mt][nt][2], col,     row + 8);
            float v11 = ep(c[mt][nt][3], col + 1, row + 8);
            if constexpr (PERMN) {
                C[(long)(row    ) * ldc + pc16(col    )] = v00;
                C[(long)(row    ) * ldc + pc16(col + 1)] = v01;
                C[(long)(row + 8) * ldc + pc16(col    )] = v10;
                C[(long)(row + 8) * ldc + pc16(col + 1)] = v11;
            } else {
                *(float2*)&C[(long)(row    ) * ldc + col] = make_float2(v00, v01);
                *(float2*)&C[(long)(row + 8) * ldc + col] = make_float2(v10, v11);
            }
        }
    }
}

// ---------------- LayerNorm; output tf32-rounded + k-permuted ---------------
__global__ void __launch_bounds__(256)
ln_perm_k(const float* __restrict__ x, const float* __restrict__ g,
          const float* __restrict__ b, float* __restrict__ o)
{
    __shared__ float red[8];
    const long row = blockIdx.x;
    const int  t = threadIdx.x, lane = t & 31, w = t >> 5;

    float4 v = ((const float4*)(x + row * DD))[t];
    float s = v.x + v.y + v.z + v.w;
    #pragma unroll
    for (int off = 16; off; off >>= 1) s += __shfl_down_sync(0xffffffffu, s, off);
    if (!lane) red[w] = s;
    __syncthreads();
    if (t == 0) { float a = 0.f; for (int i = 0; i < 8; i++) a += red[i]; red[0] = a; }
    __syncthreads();
    const float mu = red[0] * (1.0f / DD);
    __syncthreads();

    float d0 = v.x - mu, d1 = v.y - mu, d2 = v.z - mu, d3 = v.w - mu;
    float sq = d0*d0 + d1*d1 + d2*d2 + d3*d3;
    #pragma unroll
    for (int off = 16; off; off >>= 1) sq += __shfl_down_sync(0xffffffffu, sq, off);
    if (!lane) red[w] = sq;
    __syncthreads();
    if (t == 0) { float a = 0.f; for (int i = 0; i < 8; i++) a += red[i]; red[0] = a; }
    __syncthreads();
    const float rs = rsqrtf(red[0] * (1.0f / DD) + 1e-5f);

    float4 g4 = ((const float4*)g)[t];
    float4 b4 = ((const float4*)b)[t];
    float r0 = roundtf(d0 * rs * g4.x + b4.x);
    float r1 = roundtf(d1 * rs * g4.y + b4.y);
    float r2 = roundtf(d2 * rs * g4.z + b4.z);
    float r3 = roundtf(d3 * rs * g4.w + b4.w);
    // cols 4t..4t+3 -> permuted positions (t>>2)*16 + 4j + (t&3)
    float* orow = o + row * DD + (t >> 2) * 16 + (t & 3);
    orow[0]  = r0;
    orow[4]  = r1;
    orow[8]  = r2;
    orow[12] = r3;
}

// ---------------- row softmax over S=1024, in-place (exact fp32) ------------
__global__ void __launch_bounds__(256)
softmax_k(float* __restrict__ a)
{
    __shared__ float red[8];
    const long row = blockIdx.x;
    const int  t = threadIdx.x, lane = t & 31, w = t >> 5;

    float4* p = (float4*)(a + row * (long)SS);
    float4 v = p[t];
    float mx = fmaxf(fmaxf(v.x, v.y), fmaxf(v.z, v.w));
    #pragma unroll
    for (int off = 16; off; off >>= 1)
        mx = fmaxf(mx, __shfl_down_sync(0xffffffffu, mx, off));
    if (!lane) red[w] = mx;
    __syncthreads();
    if (t == 0) { float m = red[0]; for (int i = 1; i < 8; i++) m = fmaxf(m, red[i]); red[0] = m; }
    __syncthreads();
    const float rmax = red[0];
    __syncthreads();

    float e0 = __expf(v.x - rmax), e1 = __expf(v.y - rmax);
    float e2 = __expf(v.z - rmax), e3 = __expf(v.w - rmax);
    float s = e0 + e1 + e2 + e3;
    #pragma unroll
    for (int off = 16; off; off >>= 1) s += __shfl_down_sync(0xffffffffu, s, off);
    if (!lane) red[w] = s;
    __syncthreads();
    if (t == 0) { float a2 = 0.f; for (int i = 0; i < 8; i++) a2 += red[i]; red[0] = a2; }
    __syncthreads();
    const float inv = 1.0f / red[0];

    p[t] = make_float4(e0 * inv, e1 * inv, e2 * inv, e3 * inv);
}

// ---------------- host orchestration ----------------------------------------
extern "C" void kernel_launch(void* const* d_in, const int* in_sizes, int n_in,
                              void* d_out, int out_size)
{
    const float* x    = (const float*)d_in[0];
    const int*   mask = (const int*)  d_in[1];
    const float* Wq = (const float*)d_in[2];  const float* bq = (const float*)d_in[3];
    const float* Wk = (const float*)d_in[4];  const float* bk = (const float*)d_in[5];
    const float* Wv = (const float*)d_in[6];  const float* bv = (const float*)d_in[7];
    const float* Wo = (const float*)d_in[8];  const float* bo = (const float*)d_in[9];
    const float* lag = (const float*)d_in[10]; const float* lab = (const float*)d_in[11];
    const float* W1 = (const float*)d_in[12]; const float* b1 = (const float*)d_in[13];
    const float* W2 = (const float*)d_in[14]; const float* b2 = (const float*)d_in[15];
    const float* lfg = (const float*)d_in[16]; const float* lfb = (const float*)d_in[17];
    const float* bnffg = (const float*)d_in[18]; const float* bnffb = (const float*)d_in[19];
    const float* bnffm = (const float*)d_in[20]; const float* bnffv = (const float*)d_in[21];
    const float* bn1g = (const float*)d_in[22]; const float* bn1b = (const float*)d_in[23];
    const float* bn1m = (const float*)d_in[24]; const float* bn1v = (const float*)d_in[25];
    const float* bn2g = (const float*)d_in[26]; const float* bn2b = (const float*)d_in[27];
    const float* bn2m = (const float*)d_in[28]; const float* bn2v = (const float*)d_in[29];

    float *xq, *xr, *q, *k, *v, *ctx, *x1, *h, *w;
    cudaGetSymbolAddress((void**)&xq,  g_xq);
    cudaGetSymbolAddress((void**)&xr,  g_xr);
    cudaGetSymbolAddress((void**)&q,   g_q);
    cudaGetSymbolAddress((void**)&k,   g_k);
    cudaGetSymbolAddress((void**)&v,   g_v);
    cudaGetSymbolAddress((void**)&ctx, g_ctx);
    cudaGetSymbolAddress((void**)&x1,  g_x1);
    cudaGetSymbolAddress((void**)&h,   g_h);
    cudaGetSymbolAddress((void**)&w,   g_w);

    float* cWq = w;
    float* cWk = w + 1*1024*1024;
    float* cWv = w + 2*1024*1024;
    float* cWo = w + 3*1024*1024;
    float* cW1 = w + 4*1024*1024;
    float* cW2 = w + 8*1024*1024;

    float* outx = (float*)d_out;                    // [B,S,D]
    float* outa = outx + (long)NTOK * DD;           // [B,H,S,S]

    // smem: VEC stage = (128 + 128) rows * 16 floats; AV stage = 128*20 + 16*68
    constexpr int SM_VEC = 5 * (128*16 + 128*16) * 4;   // 81920 B
    constexpr int SM_AV  = 5 * (128*20 + 16*68) * 4;    // 72960 B

    //                 BM  BN  WM WN  BT    MODE CVTA  VEC   PERMN  RND
    auto* kQK = gemm_tc<128,128,64,32,true ,0,   false,true ,true , true >; // q,k (perm dk)
    auto* kV  = gemm_tc<128,128,64,32,true ,0,   false,true ,false, true >; // v   (natural)
    auto* kS  = gemm_tc<128,128,64,32,true ,3,   false,true ,false, false>; // scores
    auto* kAV = gemm_tc<128, 64,32,32,false,4,   true ,false,true , true >; // attn@V -> ctx perm
    auto* kR  = gemm_tc<128,128,64,32,true ,1,   false,true ,false, false>; // O-proj / W2 (+res+BN)
    auto* kG  = gemm_tc<128,128,64,32,true ,2,   false,true ,true , true >; // W1 (+GELU+BN) -> h perm
    cudaFuncSetAttribute((const void*)kQK, cudaFuncAttributeMaxDynamicSharedMemorySize, SM_VEC);
    cudaFuncSetAttribute((const void*)kV,  cudaFuncAttributeMaxDynamicSharedMemorySize, SM_VEC);
    cudaFuncSetAttribute((const void*)kS,  cudaFuncAttributeMaxDynamicSharedMemorySize, SM_VEC);
    cudaFuncSetAttribute((const void*)kAV, cudaFuncAttributeMaxDynamicSharedMemorySize, SM_AV);
    cudaFuncSetAttribute((const void*)kR,  cudaFuncAttributeMaxDynamicSharedMemorySize, SM_VEC);
    cudaFuncSetAttribute((const void*)kG,  cudaFuncAttributeMaxDynamicSharedMemorySize, SM_VEC);

    // 0) pre-round + k-permute weights and x
    round_perm_k<<<(1024*1024/16 + 255)/256, 256>>>(Wq, cWq, 1024*1024/16);
    round_perm_k<<<(1024*1024/16 + 255)/256, 256>>>(Wk, cWk, 1024*1024/16);
    round_perm_k<<<(1024*1024/16 + 255)/256, 256>>>(Wv, cWv, 1024*1024/16);
    round_perm_k<<<(1024*1024/16 + 255)/256, 256>>>(Wo, cWo, 1024*1024/16);
    round_perm_k<<<(4*1024*1024/16 + 255)/256, 256>>>(W1, cW1, 4*1024*1024/16);
    round_perm_k<<<(4*1024*1024/16 + 255)/256, 256>>>(W2, cW2, 4*1024*1024/16);
    round_perm_k<<<(NTOK*DD/16 + 255)/256, 256>>>(x, xr, NTOK*DD/16);

    // 1) pre-LN for query path (rounded + permuted)
    ln_perm_k<<<NTOK, 256>>>(x, lag, lab, xq);

    // 2) Q,K,V projections; q,k outputs permuted in dk, v natural
    dim3 gP(DD / 128, NTOK / 128, 1);
    kQK<<<gP, 256, SM_VEC>>>(xq, DD,0,0, cWq, DD,0,0, q, DD,0,0, DD,
        bq, nullptr, nullptr,nullptr,nullptr,nullptr, nullptr,0);
    kQK<<<gP, 256, SM_VEC>>>(xr, DD,0,0, cWk, DD,0,0, k, DD,0,0, DD,
        bk, nullptr, nullptr,nullptr,nullptr,nullptr, nullptr,0);
    kV <<<gP, 256, SM_VEC>>>(xr, DD,0,0, cWv, DD,0,0, v, DD,0,0, DD,
        bv, nullptr, nullptr,nullptr,nullptr,nullptr, nullptr,0);

    // 3) scores = Q K^T / 8 (+mask) into d_out attn region (natural layout)
    dim3 gS(SS / 128, SS / 128, BB * HH);
    kS<<<gS, 256, SM_VEC>>>(
        q, DD, (long)SS * DD, 64,
        k, DD, (long)SS * DD, 64,
        outa, SS, (long)HH * SS * SS, (long)SS * SS,
        DKK, nullptr, nullptr, nullptr,nullptr,nullptr,nullptr, mask, SS);

    // 4) softmax in place (attn output; exact fp32)
    softmax_k<<<BB * HH * SS, 256>>>(outa);

    // 5) context = attn @ V (scalar path; attn cvt in-loop); ctx written permuted
    dim3 gC(1, SS / 128, BB * HH);
    kAV<<<gC, 256, SM_AV>>>(
        outa, SS, (long)HH * SS * SS, (long)SS * SS,
        v,    DD, (long)SS * DD, 64,
        ctx,  DD, (long)SS * DD, 64,
        SS, nullptr, nullptr, nullptr,nullptr,nullptr,nullptr, nullptr,0);

    // 6) O projection + residual(x) + bn1 -> x1 (natural, exact fp32)
    kR<<<gP, 256, SM_VEC>>>(ctx, DD,0,0, cWo, DD,0,0, x1, DD,0,0, DD,
        bo, x, bn1g,bn1b,bn1m,bn1v, nullptr,0);

    // 7) FFN pre-LN (rounded + permuted)
    ln_perm_k<<<NTOK, 256>>>(x1, lfg, lfb, xq);

    // 8) h = bnff(gelu(xn W1^T + b1)), permuted  M=8192 N=4096 K=1024
    dim3 g1(DF / 128, NTOK / 128, 1);
    kG<<<g1, 256, SM_VEC>>>(xq, DD,0,0, cW1, DD,0,0, h, DF,0,0, DD,
        b1, nullptr, bnffg,bnffb,bnffm,bnffv, nullptr,0);

    // 9) out_x = bn2(h W2^T + b2 + x1)  M=8192 N=1024 K=4096
    dim3 g2(DD / 128, NTOK / 128, 1);
    kR<<<g2, 256, SM_VEC>>>(h, DF,0,0, cW2, DF,0,0, outx, DD,0,0, DF,
        b2, x1, bn2g,bn2b,bn2m,bn2v, nullptr,0);
}

// round 7
// speedup vs baseline: 1.5445x; 1.5445x over previous
#include <cuda_runtime.h>
#include <cuda_fp16.h>
#include <math.h>
#include <stdint.h>

#define BB   8
#define SS   1024
#define DD   1024
#define HH   16
#define DKK  64
#define DF   4096
#define NTOK (BB*SS)        // 8192 tokens

// ---------------- scratch (static device globals; no allocation) ------------
__device__ __half g_xq[NTOK*DD];       // LN output (half), both LNs
__device__ __half g_xr[NTOK*DD];       // x as half
__device__ __half g_q [NTOK*DD];
__device__ __half g_k [NTOK*DD];
__device__ __half g_v [NTOK*DD];       // [token, D] natural
__device__ __half g_vt[NTOK*DD];       // [b,h][dk][token] transposed
__device__ __half g_ctx[NTOK*DD];
__device__ float  g_x1[NTOK*DD];       // after bn1 (exact fp32)
__device__ __half g_h [NTOK*DF];       // FFN hidden
__device__ __half g_w [12*1024*1024];  // half weights: Wq Wk Wv Wo | W1 | W2

// ---------------- helpers ----------------------------------------------------
__device__ __forceinline__ void cpa16(void* s, const void* g) {
    unsigned sa = (unsigned)__cvta_generic_to_shared(s);
    asm volatile("cp.async.cg.shared.global [%0], [%1], 16;" :: "r"(sa), "l"(g));
}
__device__ __forceinline__ void cp_commit() { asm volatile("cp.async.commit_group;"); }
template<int N> __device__ __forceinline__ void cp_wait() {
    asm volatile("cp.async.wait_group %0;" :: "n"(N));
}
__device__ __forceinline__ void mma16(float* c, const unsigned* a, const unsigned* b) {
    asm volatile(
        "mma.sync.aligned.m16n8k16.row.col.f32.f16.f16.f32 "
        "{%0,%1,%2,%3}, {%4,%5,%6,%7}, {%8,%9}, {%0,%1,%2,%3};"
        : "+f"(c[0]), "+f"(c[1]), "+f"(c[2]), "+f"(c[3])
        : "r"(a[0]), "r"(a[1]), "r"(a[2]), "r"(a[3]), "r"(b[0]), "r"(b[1]));
}
__device__ __forceinline__ unsigned packh2(float lo, float hi) {
    __half2 h = __floats2half2_rn(lo, hi);
    return *reinterpret_cast<unsigned*>(&h);
}

// ---------------- fp16 tensor-core GEMM (3-stage cp.async, NT) ---------------
// C[M,N] = A[M,K] * B[N,K]^T + epilogue.  B always half [N,K] row-major.
// AF32: A operand in smem is fp32 (attn); packed to f16x2 in-loop.
// OUTH: store output as half (else fp32).
// MODE: 0 bias | 1 bias+res+BN | 2 bias+GELU+BN | 3 mask-scale | 4 raw
template<int BM,int BN,int WM,int WN,int MODE,bool AF32,bool OUTH>
__global__ void __launch_bounds__(256)
gemm_h(const void* __restrict__ Av, int lda, long aS1, long aS2,
       const __half* __restrict__ B, int ldb, long bS1, long bS2,
       void* __restrict__ Cv, int ldc, long cS1, long cS2,
       int K,
       const float* __restrict__ bias,
       const float* __restrict__ res, int ldres,
       const float* __restrict__ bng, const float* __restrict__ bnb,
       const float* __restrict__ bnm, const float* __restrict__ bnv,
       const int*   __restrict__ mask, int maskS1)
{
    constexpr int BK = 32;                 // k per stage (2 slabs of 16)
    constexpr int ST = 3;
    constexpr int ASTR = AF32 ? 36 : 40;   // row stride, elements
    constexpr int ASZ  = AF32 ? BM * 144 : BM * 80;   // bytes/stage
    constexpr int BSZ  = BN * 80;

    extern __shared__ char smem[];
    char* sA = smem;
    char* sB = smem + ST * ASZ;

    const int z  = blockIdx.z;
    const int zb = z >> 4;
    const int zh = z & 15;
    const char* Abase = (const char*)Av;
    if constexpr (AF32) Abase += ((long)zb * aS1 + (long)zh * aS2) * 4;
    else                Abase += ((long)zb * aS1 + (long)zh * aS2) * 2;
    B += (long)zb * bS1 + (long)zh * bS2;

    const int tid = threadIdx.x;
    const int m0  = blockIdx.y * BM;
    const int n0  = blockIdx.x * BN;

    const int warp = tid >> 5, lane = tid & 31;
    constexpr int WGN = BN / WN;
    const int wm = warp / WGN, wn = warp % WGN;
    const int g  = lane >> 2,  t  = lane & 3;
    constexpr int MT  = WM / 16;
    constexpr int NTL = WN / 8;

    float c[MT][NTL][4];
    #pragma unroll
    for (int i = 0; i < MT; i++)
        #pragma unroll
        for (int j = 0; j < NTL; j++)
            #pragma unroll
            for (int e = 0; e < 4; e++) c[i][j][e] = 0.0f;

    const int iters = K / BK;

    auto load_stage = [&](int it, int buf) {
        const int k0 = it * BK;
        char* dA = sA + buf * ASZ;
        char* dB = sB + buf * BSZ;
        if constexpr (AF32) {
            const float* Af = (const float*)Abase;
            #pragma unroll
            for (int s = tid; s < BM * 8; s += 256) {
                int row = s >> 3, seg = s & 7;
                cpa16(dA + row * 144 + seg * 16,
                      Af + (long)(m0 + row) * lda + k0 + seg * 4);
            }
        } else {
            const __half* Ah = (const __half*)Abase;
            #pragma unroll
            for (int s = tid; s < BM * 4; s += 256) {
                int row = s >> 2, seg = s & 3;
                cpa16(dA + row * 80 + seg * 16,
                      Ah + (long)(m0 + row) * lda + k0 + seg * 8);
            }
        }
        #pragma unroll
        for (int s = tid; s < BN * 4; s += 256) {
            int row = s >> 2, seg = s & 3;
            cpa16(dB + row * 80 + seg * 16,
                  B + (long)(n0 + row) * ldb + k0 + seg * 8);
        }
    };

    load_stage(0, 0);
    cp_commit();
    if (iters > 1) load_stage(1, 1);
    cp_commit();

    for (int it = 0; it < iters; ++it) {
        cp_wait<ST - 2>();
        __syncthreads();

        if (it + ST - 1 < iters) load_stage(it + ST - 1, (it + ST - 1) % ST);
        cp_commit();

        const int buf = it % ST;
        const char* bA = sA + buf * ASZ;
        const __half* Bh = (const __half*)(sB + buf * BSZ);

        #pragma unroll
        for (int ks = 0; ks < BK; ks += 16) {
            unsigned a[MT][4], b[NTL][2];
            #pragma unroll
            for (int mt = 0; mt < MT; mt++) {
                const int r = wm * WM + mt * 16 + g;
                if constexpr (AF32) {
                    const float* Af = (const float*)bA;
                    float2 f0 = *(const float2*)(Af + (r    ) * ASTR + ks + 2*t);
                    float2 f1 = *(const float2*)(Af + (r + 8) * ASTR + ks + 2*t);
                    float2 f2 = *(const float2*)(Af + (r    ) * ASTR + ks + 2*t + 8);
                    float2 f3 = *(const float2*)(Af + (r + 8) * ASTR + ks + 2*t + 8);
                    a[mt][0] = packh2(f0.x, f0.y);
                    a[mt][1] = packh2(f1.x, f1.y);
                    a[mt][2] = packh2(f2.x, f2.y);
                    a[mt][3] = packh2(f3.x, f3.y);
                } else {
                    const __half* Ah = (const __half*)bA;
                    a[mt][0] = *(const unsigned*)(Ah + (r    ) * ASTR + ks + 2*t);
                    a[mt][1] = *(const unsigned*)(Ah + (r + 8) * ASTR + ks + 2*t);
                    a[mt][2] = *(const unsigned*)(Ah + (r    ) * ASTR + ks + 2*t + 8);
                    a[mt][3] = *(const unsigned*)(Ah + (r + 8) * ASTR + ks + 2*t + 8);
                }
            }
            #pragma unroll
            for (int nt = 0; nt < NTL; nt++) {
                const int nc = wn * WN + nt * 8 + g;
                b[nt][0] = *(const unsigned*)(Bh + nc * 40 + ks + 2*t);
                b[nt][1] = *(const unsigned*)(Bh + nc * 40 + ks + 2*t + 8);
            }
            #pragma unroll
            for (int mt = 0; mt < MT; mt++)
                #pragma unroll
                for (int nt = 0; nt < NTL; nt++)
                    mma16(c[mt][nt], a[mt], b[nt]);
        }
    }

    // ---- epilogue ----
    auto ep = [&](float v, int n, long m) -> float {
        if constexpr (MODE == 0) {
            v += bias[n];
        } else if constexpr (MODE == 1) {
            v += bias[n] + res[m * ldres + n];
            v = (v - bnm[n]) * rsqrtf(bnv[n] + 1e-5f) * bng[n] + bnb[n];
        } else if constexpr (MODE == 2) {
            v += bias[n];
            v = 0.5f * v * (1.0f + erff(v * 0.70710678118654752f));
            v = (v - bnm[n]) * rsqrtf(bnv[n] + 1e-5f) * bng[n] + bnb[n];
        } else if constexpr (MODE == 3) {
            v = (mask[(long)zb * maskS1 + n] == 0) ? -1e9f : v * 0.125f;
        }
        return v;
    };

    const long cofs = (long)zb * cS1 + (long)zh * cS2;
    #pragma unroll
    for (int mt = 0; mt < MT; mt++) {
        #pragma unroll
        for (int nt = 0; nt < NTL; nt++) {
            const int row = m0 + wm * WM + mt * 16 + g;
            const int col = n0 + wn * WN + nt * 8 + 2 * t;
            float v00 = ep(c[mt][nt][0], col,     row);
            float v01 = ep(c[mt][nt][1], col + 1, row);
            float v10 = ep(c[mt][nt][2], col,     row + 8);
            float v11 = ep(c[mt][nt][3], col + 1, row + 8);
            if constexpr (OUTH) {
                __half* Ch = (__half*)Cv + cofs;
                *(__half2*)(Ch + (long)(row    ) * ldc + col) = __floats2half2_rn(v00, v01);
                *(__half2*)(Ch + (long)(row + 8) * ldc + col) = __floats2half2_rn(v10, v11);
            } else {
                float* Cf = (float*)Cv + cofs;
                *(float2*)(Cf + (long)(row    ) * ldc + col) = make_float2(v00, v01);
                *(float2*)(Cf + (long)(row + 8) * ldc + col) = make_float2(v10, v11);
            }
        }
    }
}

// ---------------- float -> half convert (vectorized) -------------------------
__global__ void __launch_bounds__(256)
cvt_k(const float* __restrict__ in, __half* __restrict__ out, int n4)
{
    int i = blockIdx.x * 256 + threadIdx.x;
    if (i < n4) {
        float4 v = ((const float4*)in)[i];
        ((__half2*)out)[2*i]   = __floats2half2_rn(v.x, v.y);
        ((__half2*)out)[2*i+1] = __floats2half2_rn(v.z, v.w);
    }
}

// ---------------- V transpose: [b,s,h*64+dk] -> [b,h][dk][s] -----------------
__global__ void __launch_bounds__(256)
vt_k(const __half* __restrict__ v, __half* __restrict__ vt)
{
    __shared__ __half tile[64][72];
    const int z = blockIdx.z;           // b*16+h
    const int b = z >> 4, h = z & 15;
    const int s0 = blockIdx.x * 64;
    const int tid = threadIdx.x;

    #pragma unroll
    for (int p = 0; p < 2; p++) {
        int r   = p * 32 + (tid >> 3);  // token within tile
        int seg = tid & 7;
        uint4 d = *(const uint4*)(v + ((long)(b * SS + s0 + r)) * DD + h * 64 + seg * 8);
        *(uint4*)&tile[r][seg * 8] = d;
    }
    __syncthreads();
    #pragma unroll
    for (int p = 0; p < 2; p++) {
        int c   = p * 32 + (tid >> 3);  // dk
        int seg = tid & 7;
        __half tmp[8];
        #pragma unroll
        for (int j = 0; j < 8; j++) tmp[j] = tile[seg * 8 + j][c];
        *(uint4*)(vt + ((long)z * 64 + c) * SS + s0 + seg * 8) = *(uint4*)tmp;
    }
}

// ---------------- LayerNorm over D=1024; half output -------------------------
__global__ void __launch_bounds__(256)
ln_k(const float* __restrict__ x, const float* __restrict__ g,
     const float* __restrict__ b, __half* __restrict__ o)
{
    __shared__ float red[8];
    const long row = blockIdx.x;
    const int  t = threadIdx.x, lane = t & 31, w = t >> 5;

    float4 v = ((const float4*)(x + row * DD))[t];
    float s = v.x + v.y + v.z + v.w;
    #pragma unroll
    for (int off = 16; off; off >>= 1) s += __shfl_down_sync(0xffffffffu, s, off);
    if (!lane) red[w] = s;
    __syncthreads();
    if (t == 0) { float a = 0.f; for (int i = 0; i < 8; i++) a += red[i]; red[0] = a; }
    __syncthreads();
    const float mu = red[0] * (1.0f / DD);
    __syncthreads();

    float d0 = v.x - mu, d1 = v.y - mu, d2 = v.z - mu, d3 = v.w - mu;
    float sq = d0*d0 + d1*d1 + d2*d2 + d3*d3;
    #pragma unroll
    for (int off = 16; off; off >>= 1) sq += __shfl_down_sync(0xffffffffu, sq, off);
    if (!lane) red[w] = sq;
    __syncthreads();
    if (t == 0) { float a = 0.f; for (int i = 0; i < 8; i++) a += red[i]; red[0] = a; }
    __syncthreads();
    const float rs = rsqrtf(red[0] * (1.0f / DD) + 1e-5f);

    float4 g4 = ((const float4*)g)[t];
    float4 b4 = ((const float4*)b)[t];
    __half2* op = (__half2*)(o + row * DD);
    op[2*t]   = __floats2half2_rn(d0 * rs * g4.x + b4.x, d1 * rs * g4.y + b4.y);
    op[2*t+1] = __floats2half2_rn(d2 * rs * g4.z + b4.z, d3 * rs * g4.w + b4.w);
}

// ---------------- row softmax over S=1024, in-place (exact fp32) -------------
__global__ void __launch_bounds__(256)
softmax_k(float* __restrict__ a)
{
    __shared__ float red[8];
    const long row = blockIdx.x;
    const int  t = threadIdx.x, lane = t & 31, w = t >> 5;

    float4* p = (float4*)(a + row * (long)SS);
    float4 v = p[t];
    float mx = fmaxf(fmaxf(v.x, v.y), fmaxf(v.z, v.w));
    #pragma unroll
    for (int off = 16; off; off >>= 1)
        mx = fmaxf(mx, __shfl_down_sync(0xffffffffu, mx, off));
    if (!lane) red[w] = mx;
    __syncthreads();
    if (t == 0) { float m = red[0]; for (int i = 1; i < 8; i++) m = fmaxf(m, red[i]); red[0] = m; }
    __syncthreads();
    const float rmax = red[0];
    __syncthreads();

    float e0 = __expf(v.x - rmax), e1 = __expf(v.y - rmax);
    float e2 = __expf(v.z - rmax), e3 = __expf(v.w - rmax);
    float s = e0 + e1 + e2 + e3;
    #pragma unroll
    for (int off = 16; off; off >>= 1) s += __shfl_down_sync(0xffffffffu, s, off);
    if (!lane) red[w] = s;
    __syncthreads();
    if (t == 0) { float a2 = 0.f; for (int i = 0; i < 8; i++) a2 += red[i]; red[0] = a2; }
    __syncthreads();
    const float inv = 1.0f / red[0];

    p[t] = make_float4(e0 * inv, e1 * inv, e2 * inv, e3 * inv);
}

// ---------------- host orchestration ----------------------------------------
extern "C" void kernel_launch(void* const* d_in, const int* in_sizes, int n_in,
                              void* d_out, int out_size)
{
    const float* x    = (const float*)d_in[0];
    const int*   mask = (const int*)  d_in[1];
    const float* Wq = (const float*)d_in[2];  const float* bq = (const float*)d_in[3];
    const float* Wk = (const float*)d_in[4];  const float* bk = (const float*)d_in[5];
    const float* Wv = (const float*)d_in[6];  const float* bv = (const float*)d_in[7];
    const float* Wo = (const float*)d_in[8];  const float* bo = (const float*)d_in[9];
    const float* lag = (const float*)d_in[10]; const float* lab = (const float*)d_in[11];
    const float* W1 = (const float*)d_in[12]; const float* b1 = (const float*)d_in[13];
    const float* W2 = (const float*)d_in[14]; const float* b2 = (const float*)d_in[15];
    const float* lfg = (const float*)d_in[16]; const float* lfb = (const float*)d_in[17];
    const float* bnffg = (const float*)d_in[18]; const float* bnffb = (const float*)d_in[19];
    const float* bnffm = (const float*)d_in[20]; const float* bnffv = (const float*)d_in[21];
    const float* bn1g = (const float*)d_in[22]; const float* bn1b = (const float*)d_in[23];
    const float* bn1m = (const float*)d_in[24]; const float* bn1v = (const float*)d_in[25];
    const float* bn2g = (const float*)d_in[26]; const float* bn2b = (const float*)d_in[27];
    const float* bn2m = (const float*)d_in[28]; const float* bn2v = (const float*)d_in[29];

    __half *xq, *xr, *q, *k, *v, *vt, *ctx, *h, *w;
    float *x1;
    cudaGetSymbolAddress((void**)&xq,  g_xq);
    cudaGetSymbolAddress((void**)&xr,  g_xr);
    cudaGetSymbolAddress((void**)&q,   g_q);
    cudaGetSymbolAddress((void**)&k,   g_k);
    cudaGetSymbolAddress((void**)&v,   g_v);
    cudaGetSymbolAddress((void**)&vt,  g_vt);
    cudaGetSymbolAddress((void**)&ctx, g_ctx);
    cudaGetSymbolAddress((void**)&x1,  g_x1);
    cudaGetSymbolAddress((void**)&h,   g_h);
    cudaGetSymbolAddress((void**)&w,   g_w);

    __half* cWq = w;
    __half* cWk = w + 1*1024*1024;
    __half* cWv = w + 2*1024*1024;
    __half* cWo = w + 3*1024*1024;
    __half* cW1 = w + 4*1024*1024;
    __half* cW2 = w + 8*1024*1024;

    float* outx = (float*)d_out;                    // [B,S,D]
    float* outa = outx + (long)NTOK * DD;           // [B,H,S,S]

    constexpr int SM_H  = 3 * (128*80 + 128*80);    // 61440 B
    constexpr int SM_AV = 3 * (128*144 + 64*80);    // 70656 B

    //                 BM  BN  WM WN  MODE AF32  OUTH
    auto* kP  = gemm_h<128,128,64,32, 0,   false,true >;  // QKV -> half
    auto* kS  = gemm_h<128,128,64,32, 3,   false,false>;  // scores -> fp32
    auto* kAV = gemm_h<128, 64,32,32, 4,   true ,true >;  // attn@Vt -> ctx half
    auto* kR  = gemm_h<128,128,64,32, 1,   false,false>;  // O-proj / W2 -> fp32
    auto* kG  = gemm_h<128,128,64,32, 2,   false,true >;  // W1 -> h half
    cudaFuncSetAttribute((const void*)kP,  cudaFuncAttributeMaxDynamicSharedMemorySize, SM_H);
    cudaFuncSetAttribute((const void*)kS,  cudaFuncAttributeMaxDynamicSharedMemorySize, SM_H);
    cudaFuncSetAttribute((const void*)kAV, cudaFuncAttributeMaxDynamicSharedMemorySize, SM_AV);
    cudaFuncSetAttribute((const void*)kR,  cudaFuncAttributeMaxDynamicSharedMemorySize, SM_H);
    cudaFuncSetAttribute((const void*)kG,  cudaFuncAttributeMaxDynamicSharedMemorySize, SM_H);

    // 0) convert weights + x to half
    cvt_k<<<(1024*1024/4 + 255)/256, 256>>>(Wq, cWq, 1024*1024/4);
    cvt_k<<<(1024*1024/4 + 255)/256, 256>>>(Wk, cWk, 1024*1024/4);
    cvt_k<<<(1024*1024/4 + 255)/256, 256>>>(Wv, cWv, 1024*1024/4);
    cvt_k<<<(1024*1024/4 + 255)/256, 256>>>(Wo, cWo, 1024*1024/4);
    cvt_k<<<(4*1024*1024/4 + 255)/256, 256>>>(W1, cW1, 4*1024*1024/4);
    cvt_k<<<(4*1024*1024/4 + 255)/256, 256>>>(W2, cW2, 4*1024*1024/4);
    cvt_k<<<(NTOK*DD/4 + 255)/256, 256>>>(x, xr, NTOK*DD/4);

    // 1) pre-LN for query path (half out)
    ln_k<<<NTOK, 256>>>(x, lag, lab, xq);

    // 2) Q,K,V projections (M=8192 N=1024 K=1024), outputs half
    dim3 gP(DD / 128, NTOK / 128, 1);
    kP<<<gP, 256, SM_H>>>(xq, DD,0,0, cWq, DD,0,0, q, DD,0,0, DD,
        bq, nullptr,0, nullptr,nullptr,nullptr,nullptr, nullptr,0);
    kP<<<gP, 256, SM_H>>>(xr, DD,0,0, cWk, DD,0,0, k, DD,0,0, DD,
        bk, nullptr,0, nullptr,nullptr,nullptr,nullptr, nullptr,0);
    kP<<<gP, 256, SM_H>>>(xr, DD,0,0, cWv, DD,0,0, v, DD,0,0, DD,
        bv, nullptr,0, nullptr,nullptr,nullptr,nullptr, nullptr,0);

    // 2b) transpose V per (b,h): [s, dk] -> [dk, s]
    dim3 gV(SS / 64, 1, BB * HH);
    vt_k<<<gV, 256>>>(v, vt);

    // 3) scores = Q K^T / 8 (+mask) into d_out attn region
    dim3 gS(SS / 128, SS / 128, BB * HH);
    kS<<<gS, 256, SM_H>>>(
        q, DD, (long)SS * DD, 64,
        k, DD, (long)SS * DD, 64,
        outa, SS, (long)HH * SS * SS, (long)SS * SS,
        DKK, nullptr, nullptr,0, nullptr,nullptr,nullptr,nullptr, mask, SS);

    // 4) softmax in place (this IS the attn output; exact fp32)
    softmax_k<<<BB * HH * SS, 256>>>(outa);

    // 5) context = attn @ V  (A fp32 attn, B = vt half [dk, s])
    dim3 gC(1, SS / 128, BB * HH);
    kAV<<<gC, 256, SM_AV>>>(
        outa, SS, (long)HH * SS * SS, (long)SS * SS,
        vt,   SS, (long)HH * DKK * SS, (long)DKK * SS,
        ctx,  DD, (long)SS * DD, 64,
        SS, nullptr, nullptr,0, nullptr,nullptr,nullptr,nullptr, nullptr,0);

    // 6) O projection + residual(x) + bn1 -> x1 (fp32)
    kR<<<gP, 256, SM_H>>>(ctx, DD,0,0, cWo, DD,0,0, x1, DD,0,0, DD,
        bo, x, DD, bn1g,bn1b,bn1m,bn1v, nullptr,0);

    // 7) FFN pre-LN (half out)
    ln_k<<<NTOK, 256>>>(x1, lfg, lfb, xq);

    // 8) h = bnff(gelu(xn W1^T + b1)) -> half  M=8192 N=4096 K=1024
    dim3 g1(DF / 128, NTOK / 128, 1);
    kG<<<g1, 256, SM_H>>>(xq, DD,0,0, cW1, DD,0,0, h, DF,0,0, DD,
        b1, nullptr,0, bnffg,bnffb,bnffm,bnffv, nullptr,0);

    // 9) out_x = bn2(h W2^T + b2 + x1)  M=8192 N=1024 K=4096
    dim3 g2(DD / 128, NTOK / 128, 1);
    kR<<<g2, 256, SM_H>>>(h, DF,0,0, cW2, DF,0,0, outx, DD,0,0, DF,
        b2, x1, DD, bn2g,bn2b,bn2m,bn2v, nullptr,0);
}

// round 8
// speedup vs baseline: 1.6726x; 1.0829x over previous
#include <cuda_runtime.h>
#include <cuda_fp16.h>
#include <math.h>
#include <stdint.h>

#define BB   8
#define SS   1024
#define DD   1024
#define HH   16
#define DKK  64
#define DF   4096
#define NTOK (BB*SS)        // 8192 tokens

// ---------------- scratch (static device globals; no allocation) ------------
__device__ __half g_xq[NTOK*DD];       // LN output (half), both LNs
__device__ __half g_xr[NTOK*DD];       // x as half
__device__ __half g_q [NTOK*DD];
__device__ __half g_k [NTOK*DD];
__device__ __half g_v [NTOK*DD];       // [token, D] natural
__device__ __half g_vt[NTOK*DD];       // [b,h][dk][token] transposed
__device__ __half g_ctx[NTOK*DD];
__device__ float  g_x1[NTOK*DD];       // after bn1 (exact fp32)
__device__ __half g_h [NTOK*DF];       // FFN hidden
__device__ __half g_w [12*1024*1024];  // half weights: Wq Wk Wv Wo | W1 | W2
__device__ __half g_ah[134217728];     // attn as half (B*H*S*S) for AV GEMM

// ---------------- helpers ----------------------------------------------------
__device__ __forceinline__ void cpa16(void* s, const void* g) {
    unsigned sa = (unsigned)__cvta_generic_to_shared(s);
    asm volatile("cp.async.cg.shared.global [%0], [%1], 16;" :: "r"(sa), "l"(g));
}
__device__ __forceinline__ void cp_commit() { asm volatile("cp.async.commit_group;"); }
template<int N> __device__ __forceinline__ void cp_wait() {
    asm volatile("cp.async.wait_group %0;" :: "n"(N));
}
__device__ __forceinline__ void mma16(float* c, const unsigned* a, const unsigned* b) {
    asm volatile(
        "mma.sync.aligned.m16n8k16.row.col.f32.f16.f16.f32 "
        "{%0,%1,%2,%3}, {%4,%5,%6,%7}, {%8,%9}, {%0,%1,%2,%3};"
        : "+f"(c[0]), "+f"(c[1]), "+f"(c[2]), "+f"(c[3])
        : "r"(a[0]), "r"(a[1]), "r"(a[2]), "r"(a[3]), "r"(b[0]), "r"(b[1]));
}
__device__ __forceinline__ void ldm4(unsigned* r, uint32_t addr) {
    asm volatile("ldmatrix.sync.aligned.m8n8.x4.shared.b16 {%0,%1,%2,%3}, [%4];"
                 : "=r"(r[0]), "=r"(r[1]), "=r"(r[2]), "=r"(r[3]) : "r"(addr));
}

// ---------------- fp16 tensor-core GEMM (3-stage cp.async + ldmatrix, NT) ----
// C[M,N] = A[M,K] * B[N,K]^T + epilogue. A,B half, K-major.
// OUTH: store output as half (else fp32).
// MODE: 0 bias | 1 bias+res+BN | 2 bias+GELU+BN | 3 mask-scale | 4 raw
template<int BM,int BN,int WM,int WN,int MODE,bool OUTH>
__global__ void __launch_bounds__(256)
gemm_h(const __half* __restrict__ A, int lda, long aS1, long aS2,
       const __half* __restrict__ B, int ldb, long bS1, long bS2,
       void* __restrict__ Cv, int ldc, long cS1, long cS2,
       int K,
       const float* __restrict__ bias,
       const float* __restrict__ res, int ldres,
       const float* __restrict__ bng, const float* __restrict__ bnb,
       const float* __restrict__ bnm, const float* __restrict__ bnv,
       const int*   __restrict__ mask, int maskS1)
{
    constexpr int BK  = 32;              // k per stage (2 slabs of 16)
    constexpr int ST  = 3;
    constexpr int ASZ = BM * 80;         // bytes/stage (row stride 40 halves)
    constexpr int BSZ = BN * 80;

    extern __shared__ char smem[];
    const uint32_t smem_u = (uint32_t)__cvta_generic_to_shared(smem);

    const int z  = blockIdx.z;
    const int zb = z >> 4;
    const int zh = z & 15;
    A += (long)zb * aS1 + (long)zh * aS2;
    B += (long)zb * bS1 + (long)zh * bS2;

    const int tid = threadIdx.x;
    const int m0  = blockIdx.y * BM;
    const int n0  = blockIdx.x * BN;

    const int warp = tid >> 5, lane = tid & 31;
    constexpr int WGN = BN / WN;
    const int wm = warp / WGN, wn = warp % WGN;
    const int g  = lane >> 2,  t  = lane & 3;
    constexpr int MT  = WM / 16;
    constexpr int NTL = WN / 8;          // must be 4 here (2x ldm4 for B)

    // ldmatrix per-lane source offsets (bytes within a stage)
    const int arow  = (lane & 7) | (((lane >> 3) & 1) << 3);
    const int akofs = (lane >> 4) << 3;
    const int brow  = ((lane >> 4) << 3) | (lane & 7);
    const int bkofs = ((lane >> 3) & 1) << 3;
    uint32_t aoff[MT], boff[NTL/2];
    #pragma unroll
    for (int mt = 0; mt < MT; mt++)
        aoff[mt] = ((wm * WM + mt * 16 + arow) * 40 + akofs) * 2;
    #pragma unroll
    for (int p = 0; p < NTL/2; p++)
        boff[p] = ((wn * WN + p * 16 + brow) * 40 + bkofs) * 2;

    float c[MT][NTL][4];
    #pragma unroll
    for (int i = 0; i < MT; i++)
        #pragma unroll
        for (int j = 0; j < NTL; j++)
            #pragma unroll
            for (int e = 0; e < 4; e++) c[i][j][e] = 0.0f;

    const int iters = K / BK;

    auto load_stage = [&](int it, int buf) {
        const int k0 = it * BK;
        char* dA = smem + buf * ASZ;
        char* dB = smem + ST * ASZ + buf * BSZ;
        #pragma unroll
        for (int s = tid; s < BM * 4; s += 256) {
            int row = s >> 2, seg = s & 3;
            cpa16(dA + row * 80 + seg * 16,
                  A + (long)(m0 + row) * lda + k0 + seg * 8);
        }
        #pragma unroll
        for (int s = tid; s < BN * 4; s += 256) {
            int row = s >> 2, seg = s & 3;
            cpa16(dB + row * 80 + seg * 16,
                  B + (long)(n0 + row) * ldb + k0 + seg * 8);
        }
    };

    load_stage(0, 0);
    cp_commit();
    if (iters > 1) load_stage(1, 1);
    cp_commit();

    for (int it = 0; it < iters; ++it) {
        cp_wait<ST - 2>();
        __syncthreads();

        if (it + ST - 1 < iters) load_stage(it + ST - 1, (it + ST - 1) % ST);
        cp_commit();

        const int buf = it % ST;
        const uint32_t aBase = smem_u + buf * ASZ;
        const uint32_t bBase = smem_u + ST * ASZ + buf * BSZ;

        #pragma unroll
        for (int ks = 0; ks < BK; ks += 16) {
            unsigned a[MT][4], b[NTL/2][4];
            #pragma unroll
            for (int mt = 0; mt < MT; mt++)
                ldm4(a[mt], aBase + aoff[mt] + ks * 2);
            #pragma unroll
            for (int p = 0; p < NTL/2; p++)
                ldm4(b[p], bBase + boff[p] + ks * 2);
            #pragma unroll
            for (int mt = 0; mt < MT; mt++)
                #pragma unroll
                for (int p = 0; p < NTL/2; p++) {
                    mma16(c[mt][2*p],   a[mt], &b[p][0]);
                    mma16(c[mt][2*p+1], a[mt], &b[p][2]);
                }
        }
    }

    // ---- epilogue ----
    auto ep = [&](float v, int n, long m) -> float {
        if constexpr (MODE == 0) {
            v += bias[n];
        } else if constexpr (MODE == 1) {
            v += bias[n] + res[m * ldres + n];
            v = (v - bnm[n]) * rsqrtf(bnv[n] + 1e-5f) * bng[n] + bnb[n];
        } else if constexpr (MODE == 2) {
            v += bias[n];
            v = 0.5f * v * (1.0f + erff(v * 0.70710678118654752f));
            v = (v - bnm[n]) * rsqrtf(bnv[n] + 1e-5f) * bng[n] + bnb[n];
        } else if constexpr (MODE == 3) {
            v = (mask[(long)zb * maskS1 + n] == 0) ? -1e9f : v * 0.125f;
        }
        return v;
    };

    const long cofs = (long)zb * cS1 + (long)zh * cS2;
    #pragma unroll
    for (int mt = 0; mt < MT; mt++) {
        #pragma unroll
        for (int nt = 0; nt < NTL; nt++) {
            const int row = m0 + wm * WM + mt * 16 + g;
            const int col = n0 + wn * WN + nt * 8 + 2 * t;
            float v00 = ep(c[mt][nt][0], col,     row);
            float v01 = ep(c[mt][nt][1], col + 1, row);
            float v10 = ep(c[mt][nt][2], col,     row + 8);
            float v11 = ep(c[mt][nt][3], col + 1, row + 8);
            if constexpr (OUTH) {
                __half* Ch = (__half*)Cv + cofs;
                *(__half2*)(Ch + (long)(row    ) * ldc + col) = __floats2half2_rn(v00, v01);
                *(__half2*)(Ch + (long)(row + 8) * ldc + col) = __floats2half2_rn(v10, v11);
            } else {
                float* Cf = (float*)Cv + cofs;
                *(float2*)(Cf + (long)(row    ) * ldc + col) = make_float2(v00, v01);
                *(float2*)(Cf + (long)(row + 8) * ldc + col) = make_float2(v10, v11);
            }
        }
    }
}

// ---------------- float -> half convert (vectorized) -------------------------
__global__ void __launch_bounds__(256)
cvt_k(const float* __restrict__ in, __half* __restrict__ out, int n4)
{
    int i = blockIdx.x * 256 + threadIdx.x;
    if (i < n4) {
        float4 v = ((const float4*)in)[i];
        ((__half2*)out)[2*i]   = __floats2half2_rn(v.x, v.y);
        ((__half2*)out)[2*i+1] = __floats2half2_rn(v.z, v.w);
    }
}

// ---------------- V transpose: [b,s,h*64+dk] -> [b,h][dk][s] -----------------
__global__ void __launch_bounds__(256)
vt_k(const __half* __restrict__ v, __half* __restrict__ vt)
{
    __shared__ __half tile[64][72];
    const int z = blockIdx.z;           // b*16+h
    const int b = z >> 4, h = z & 15;
    const int s0 = blockIdx.x * 64;
    const int tid = threadIdx.x;

    #pragma unroll
    for (int p = 0; p < 2; p++) {
        int r   = p * 32 + (tid >> 3);
        int seg = tid & 7;
        uint4 d = *(const uint4*)(v + ((long)(b * SS + s0 + r)) * DD + h * 64 + seg * 8);
        *(uint4*)&tile[r][seg * 8] = d;
    }
    __syncthreads();
    #pragma unroll
    for (int p = 0; p < 2; p++) {
        int c   = p * 32 + (tid >> 3);
        int seg = tid & 7;
        __half tmp[8];
        #pragma unroll
        for (int j = 0; j < 8; j++) tmp[j] = tile[seg * 8 + j][c];
        *(uint4*)(vt + ((long)z * 64 + c) * SS + s0 + seg * 8) = *(uint4*)tmp;
    }
}

// ---------------- LayerNorm over D=1024; half output -------------------------
__global__ void __launch_bounds__(256)
ln_k(const float* __restrict__ x, const float* __restrict__ g,
     const float* __restrict__ b, __half* __restrict__ o)
{
    __shared__ float red[8];
    const long row = blockIdx.x;
    const int  t = threadIdx.x, lane = t & 31, w = t >> 5;

    float4 v = ((const float4*)(x + row * DD))[t];
    float s = v.x + v.y + v.z + v.w;
    #pragma unroll
    for (int off = 16; off; off >>= 1) s += __shfl_down_sync(0xffffffffu, s, off);
    if (!lane) red[w] = s;
    __syncthreads();
    if (t == 0) { float a = 0.f; for (int i = 0; i < 8; i++) a += red[i]; red[0] = a; }
    __syncthreads();
    const float mu = red[0] * (1.0f / DD);
    __syncthreads();

    float d0 = v.x - mu, d1 = v.y - mu, d2 = v.z - mu, d3 = v.w - mu;
    float sq = d0*d0 + d1*d1 + d2*d2 + d3*d3;
    #pragma unroll
    for (int off = 16; off; off >>= 1) sq += __shfl_down_sync(0xffffffffu, sq, off);
    if (!lane) red[w] = sq;
    __syncthreads();
    if (t == 0) { float a = 0.f; for (int i = 0; i < 8; i++) a += red[i]; red[0] = a; }
    __syncthreads();
    const float rs = rsqrtf(red[0] * (1.0f / DD) + 1e-5f);

    float4 g4 = ((const float4*)g)[t];
    float4 b4 = ((const float4*)b)[t];
    __half2* op = (__half2*)(o + row * DD);
    op[2*t]   = __floats2half2_rn(d0 * rs * g4.x + b4.x, d1 * rs * g4.y + b4.y);
    op[2*t+1] = __floats2half2_rn(d2 * rs * g4.z + b4.z, d3 * rs * g4.w + b4.w);
}

// ---------------- row softmax over S=1024; fp32 in-place + half copy ---------
__global__ void __launch_bounds__(256)
softmax_k(float* __restrict__ a, __half* __restrict__ ah)
{
    __shared__ float red[8];
    const long row = blockIdx.x;
    const int  t = threadIdx.x, lane = t & 31, w = t >> 5;

    float4* p = (float4*)(a + row * (long)SS);
    float4 v = p[t];
    float mx = fmaxf(fmaxf(v.x, v.y), fmaxf(v.z, v.w));
    #pragma unroll
    for (int off = 16; off; off >>= 1)
        mx = fmaxf(mx, __shfl_down_sync(0xffffffffu, mx, off));
    if (!lane) red[w] = mx;
    __syncthreads();
    if (t == 0) { float m = red[0]; for (int i = 1; i < 8; i++) m = fmaxf(m, red[i]); red[0] = m; }
    __syncthreads();
    const float rmax = red[0];
    __syncthreads();

    float e0 = __expf(v.x - rmax), e1 = __expf(v.y - rmax);
    float e2 = __expf(v.z - rmax), e3 = __expf(v.w - rmax);
    float s = e0 + e1 + e2 + e3;
    #pragma unroll
    for (int off = 16; off; off >>= 1) s += __shfl_down_sync(0xffffffffu, s, off);
    if (!lane) red[w] = s;
    __syncthreads();
    if (t == 0) { float a2 = 0.f; for (int i = 0; i < 8; i++) a2 += red[i]; red[0] = a2; }
    __syncthreads();
    const float inv = 1.0f / red[0];

    float r0 = e0 * inv, r1 = e1 * inv, r2 = e2 * inv, r3 = e3 * inv;
    p[t] = make_float4(r0, r1, r2, r3);
    __half2* hp = (__half2*)(ah + row * (long)SS);
    hp[2*t]   = __floats2half2_rn(r0, r1);
    hp[2*t+1] = __floats2half2_rn(r2, r3);
}

// ---------------- host orchestration ----------------------------------------
extern "C" void kernel_launch(void* const* d_in, const int* in_sizes, int n_in,
                              void* d_out, int out_size)
{
    const float* x    = (const float*)d_in[0];
    const int*   mask = (const int*)  d_in[1];
    const float* Wq = (const float*)d_in[2];  const float* bq = (const float*)d_in[3];
    const float* Wk = (const float*)d_in[4];  const float* bk = (const float*)d_in[5];
    const float* Wv = (const float*)d_in[6];  const float* bv = (const float*)d_in[7];
    const float* Wo = (const float*)d_in[8];  const float* bo = (const float*)d_in[9];
    const float* lag = (const float*)d_in[10]; const float* lab = (const float*)d_in[11];
    const float* W1 = (const float*)d_in[12]; const float* b1 = (const float*)d_in[13];
    const float* W2 = (const float*)d_in[14]; const float* b2 = (const float*)d_in[15];
    const float* lfg = (const float*)d_in[16]; const float* lfb = (const float*)d_in[17];
    const float* bnffg = (const float*)d_in[18]; const float* bnffb = (const float*)d_in[19];
    const float* bnffm = (const float*)d_in[20]; const float* bnffv = (const float*)d_in[21];
    const float* bn1g = (const float*)d_in[22]; const float* bn1b = (const float*)d_in[23];
    const float* bn1m = (const float*)d_in[24]; const float* bn1v = (const float*)d_in[25];
    const float* bn2g = (const float*)d_in[26]; const float* bn2b = (const float*)d_in[27];
    const float* bn2m = (const float*)d_in[28]; const float* bn2v = (const float*)d_in[29];

    __half *xq, *xr, *q, *k, *v, *vt, *ctx, *h, *w, *ah;
    float *x1;
    cudaGetSymbolAddress((void**)&xq,  g_xq);
    cudaGetSymbolAddress((void**)&xr,  g_xr);
    cudaGetSymbolAddress((void**)&q,   g_q);
    cudaGetSymbolAddress((void**)&k,   g_k);
    cudaGetSymbolAddress((void**)&v,   g_v);
    cudaGetSymbolAddress((void**)&vt,  g_vt);
    cudaGetSymbolAddress((void**)&ctx, g_ctx);
    cudaGetSymbolAddress((void**)&x1,  g_x1);
    cudaGetSymbolAddress((void**)&h,   g_h);
    cudaGetSymbolAddress((void**)&w,   g_w);
    cudaGetSymbolAddress((void**)&ah,  g_ah);

    __half* cWq = w;
    __half* cWk = w + 1*1024*1024;
    __half* cWv = w + 2*1024*1024;
    __half* cWo = w + 3*1024*1024;
    __half* cW1 = w + 4*1024*1024;
    __half* cW2 = w + 8*1024*1024;

    float* outx = (float*)d_out;                    // [B,S,D]
    float* outa = outx + (long)NTOK * DD;           // [B,H,S,S]

    constexpr int SM_H  = 3 * (128*80 + 128*80);    // 61440 B
    constexpr int SM_AV = 3 * (128*80 +  64*80);    // 46080 B

    //                 BM  BN  WM WN  MODE OUTH
    auto* kP  = gemm_h<128,128,64,32, 0,   true >;  // QKV -> half
    auto* kS  = gemm_h<128,128,64,32, 3,   false>;  // scores -> fp32
    auto* kAV = gemm_h<128, 64,32,32, 4,   true >;  // attn_h @ Vt -> ctx half
    auto* kR  = gemm_h<128,128,64,32, 1,   false>;  // O-proj / W2 -> fp32
    auto* kG  = gemm_h<128,128,64,32, 2,   true >;  // W1 -> h half
    cudaFuncSetAttribute((const void*)kP,  cudaFuncAttributeMaxDynamicSharedMemorySize, SM_H);
    cudaFuncSetAttribute((const void*)kS,  cudaFuncAttributeMaxDynamicSharedMemorySize, SM_H);
    cudaFuncSetAttribute((const void*)kAV, cudaFuncAttributeMaxDynamicSharedMemorySize, SM_AV);
    cudaFuncSetAttribute((const void*)kR,  cudaFuncAttributeMaxDynamicSharedMemorySize, SM_H);
    cudaFuncSetAttribute((const void*)kG,  cudaFuncAttributeMaxDynamicSharedMemorySize, SM_H);

    // 0) convert weights + x to half
    cvt_k<<<(1024*1024/4 + 255)/256, 256>>>(Wq, cWq, 1024*1024/4);
    cvt_k<<<(1024*1024/4 + 255)/256, 256>>>(Wk, cWk, 1024*1024/4);
    cvt_k<<<(1024*1024/4 + 255)/256, 256>>>(Wv, cWv, 1024*1024/4);
    cvt_k<<<(1024*1024/4 + 255)/256, 256>>>(Wo, cWo, 1024*1024/4);
    cvt_k<<<(4*1024*1024/4 + 255)/256, 256>>>(W1, cW1, 4*1024*1024/4);
    cvt_k<<<(4*1024*1024/4 + 255)/256, 256>>>(W2, cW2, 4*1024*1024/4);
    cvt_k<<<(NTOK*DD/4 + 255)/256, 256>>>(x, xr, NTOK*DD/4);

    // 1) pre-LN for query path (half out)
    ln_k<<<NTOK, 256>>>(x, lag, lab, xq);

    // 2) Q,K,V projections (M=8192 N=1024 K=1024), outputs half
    dim3 gP(DD / 128, NTOK / 128, 1);
    kP<<<gP, 256, SM_H>>>(xq, DD,0,0, cWq, DD,0,0, q, DD,0,0, DD,
        bq, nullptr,0, nullptr,nullptr,nullptr,nullptr, nullptr,0);
    kP<<<gP, 256, SM_H>>>(xr, DD,0,0, cWk, DD,0,0, k, DD,0,0, DD,
        bk, nullptr,0, nullptr,nullptr,nullptr,nullptr, nullptr,0);
    kP<<<gP, 256, SM_H>>>(xr, DD,0,0, cWv, DD,0,0, v, DD,0,0, DD,
        bv, nullptr,0, nullptr,nullptr,nullptr,nullptr, nullptr,0);

    // 2b) transpose V per (b,h): [s, dk] -> [dk, s]
    dim3 gV(SS / 64, 1, BB * HH);
    vt_k<<<gV, 256>>>(v, vt);

    // 3) scores = Q K^T / 8 (+mask) into d_out attn region
    dim3 gS(SS / 128, SS / 128, BB * HH);
    kS<<<gS, 256, SM_H>>>(
        q, DD, (long)SS * DD, 64,
        k, DD, (long)SS * DD, 64,
        outa, SS, (long)HH * SS * SS, (long)SS * SS,
        DKK, nullptr, nullptr,0, nullptr,nullptr,nullptr,nullptr, mask, SS);

    // 4) softmax in place (fp32 attn output) + half copy for AV
    softmax_k<<<BB * HH * SS, 256>>>(outa, ah);

    // 5) context = attn_h @ Vt  (all-half NT GEMM)
    dim3 gC(1, SS / 128, BB * HH);
    kAV<<<gC, 256, SM_AV>>>(
        ah,   SS, (long)HH * SS * SS, (long)SS * SS,
        vt,   SS, (long)HH * DKK * SS, (long)DKK * SS,
        ctx,  DD, (long)SS * DD, 64,
        SS, nullptr, nullptr,0, nullptr,nullptr,nullptr,nullptr, nullptr,0);

    // 6) O projection + residual(x) + bn1 -> x1 (fp32)
    kR<<<gP, 256, SM_H>>>(ctx, DD,0,0, cWo, DD,0,0, x1, DD,0,0, DD,
        bo, x, DD, bn1g,bn1b,bn1m,bn1v, nullptr,0);

    // 7) FFN pre-LN (half out)
    ln_k<<<NTOK, 256>>>(x1, lfg, lfb, xq);

    // 8) h = bnff(gelu(xn W1^T + b1)) -> half  M=8192 N=4096 K=1024
    dim3 g1(DF / 128, NTOK / 128, 1);
    kG<<<g1, 256, SM_H>>>(xq, DD,0,0, cW1, DD,0,0, h, DF,0,0, DD,
        b1, nullptr,0, bnffg,bnffb,bnffm,bnffv, nullptr,0);

    // 9) out_x = bn2(h W2^T + b2 + x1)  M=8192 N=1024 K=4096
    dim3 g2(DD / 128, NTOK / 128, 1);
    kR<<<g2, 256, SM_H>>>(h, DF,0,0, cW2, DF,0,0, outx, DD,0,0, DF,
        b2, x1, DD, bn2g,bn2b,bn2m,bn2v, nullptr,0);
}

// round 9
// speedup vs baseline: 1.6767x; 1.0025x over previous
#include <cuda_runtime.h>
#include <cuda_fp16.h>
#include <math.h>
#include <stdint.h>

#define BB   8
#define SS   1024
#define DD   1024
#define HH   16
#define DKK  64
#define DF   4096
#define NTOK (BB*SS)        // 8192 tokens

// ---------------- scratch (static device globals; no allocation) ------------
__device__ __half g_xq[NTOK*DD];       // LN output (half), both LNs
__device__ __half g_xr[NTOK*DD];       // x as half
__device__ __half g_q [NTOK*DD];
__device__ __half g_kv[NTOK*2048];     // fused K|V: [token][0:1024)=k, [1024:2048)=v
__device__ __half g_vt[NTOK*DD];       // [b,h][dk][token] transposed V
__device__ __half g_ctx[NTOK*DD];
__device__ float  g_x1[NTOK*DD];       // after bn1 (exact fp32)
__device__ __half g_h [NTOK*DF];       // FFN hidden
__device__ __half g_w [12*1024*1024];  // half weights: Wq Wk Wv Wo | W1 | W2
__device__ __half g_ah[134217728];     // attn as half (B*H*S*S) for AV GEMM

// ---------------- helpers ----------------------------------------------------
__device__ __forceinline__ void cpa16(void* s, const void* g) {
    unsigned sa = (unsigned)__cvta_generic_to_shared(s);
    asm volatile("cp.async.cg.shared.global [%0], [%1], 16;" :: "r"(sa), "l"(g));
}
__device__ __forceinline__ void cp_commit() { asm volatile("cp.async.commit_group;"); }
template<int N> __device__ __forceinline__ void cp_wait() {
    asm volatile("cp.async.wait_group %0;" :: "n"(N));
}
__device__ __forceinline__ void mma16(float* c, const unsigned* a, const unsigned* b) {
    asm volatile(
        "mma.sync.aligned.m16n8k16.row.col.f32.f16.f16.f32 "
        "{%0,%1,%2,%3}, {%4,%5,%6,%7}, {%8,%9}, {%0,%1,%2,%3};"
        : "+f"(c[0]), "+f"(c[1]), "+f"(c[2]), "+f"(c[3])
        : "r"(a[0]), "r"(a[1]), "r"(a[2]), "r"(a[3]), "r"(b[0]), "r"(b[1]));
}
__device__ __forceinline__ void ldm4(unsigned* r, uint32_t addr) {
    asm volatile("ldmatrix.sync.aligned.m8n8.x4.shared.b16 {%0,%1,%2,%3}, [%4];"
                 : "=r"(r[0]), "=r"(r[1]), "=r"(r[2]), "=r"(r[3]) : "r"(addr));
}

// ---------------- fp16 tensor-core GEMM (ST-stage cp.async + ldmatrix, NT) ---
// C[M,N] = A[M,K] * B[N,K]^T + epilogue. A,B half, K-major.
// bias2: if non-null, cols >=1024 use bias2[n-1024] (fused KV projection).
// MODE: 0 bias | 1 bias+res+BN | 2 bias+GELU+BN | 3 mask-scale | 4 raw
template<int BM,int BN,int WM,int WN,int ST,int MODE,bool OUTH>
__global__ void __launch_bounds__(256)
gemm_h(const __half* __restrict__ A, int lda, long aS1, long aS2,
       const __half* __restrict__ B, int ldb, long bS1, long bS2,
       void* __restrict__ Cv, int ldc, long cS1, long cS2,
       int K,
       const float* __restrict__ bias, const float* __restrict__ bias2,
       const float* __restrict__ res, int ldres,
       const float* __restrict__ bng, const float* __restrict__ bnb,
       const float* __restrict__ bnm, const float* __restrict__ bnv,
       const int*   __restrict__ mask, int maskS1)
{
    constexpr int BK  = 32;              // k per stage (2 slabs of 16)
    constexpr int ASZ = BM * 80;         // bytes/stage (row stride 40 halves)
    constexpr int BSZ = BN * 80;

    extern __shared__ char smem[];
    const uint32_t smem_u = (uint32_t)__cvta_generic_to_shared(smem);

    const int z  = blockIdx.z;
    const int zb = z >> 4;
    const int zh = z & 15;
    A += (long)zb * aS1 + (long)zh * aS2;
    B += (long)zb * bS1 + (long)zh * bS2;

    const int tid = threadIdx.x;
    const int m0  = blockIdx.y * BM;
    const int n0  = blockIdx.x * BN;

    const int warp = tid >> 5, lane = tid & 31;
    constexpr int WGN = BN / WN;
    const int wm = warp / WGN, wn = warp % WGN;
    const int g  = lane >> 2,  t  = lane & 3;
    constexpr int MT  = WM / 16;
    constexpr int NTL = WN / 8;

    // ldmatrix per-lane source offsets (bytes within a stage)
    const int arow  = (lane & 7) | (((lane >> 3) & 1) << 3);
    const int akofs = (lane >> 4) << 3;
    const int brow  = ((lane >> 4) << 3) | (lane & 7);
    const int bkofs = ((lane >> 3) & 1) << 3;
    uint32_t aoff[MT], boff[NTL/2];
    #pragma unroll
    for (int mt = 0; mt < MT; mt++)
        aoff[mt] = ((wm * WM + mt * 16 + arow) * 40 + akofs) * 2;
    #pragma unroll
    for (int p = 0; p < NTL/2; p++)
        boff[p] = ((wn * WN + p * 16 + brow) * 40 + bkofs) * 2;

    float c[MT][NTL][4];
    #pragma unroll
    for (int i = 0; i < MT; i++)
        #pragma unroll
        for (int j = 0; j < NTL; j++)
            #pragma unroll
            for (int e = 0; e < 4; e++) c[i][j][e] = 0.0f;

    const int iters = K / BK;

    auto load_stage = [&](int it, int buf) {
        const int k0 = it * BK;
        char* dA = smem + buf * ASZ;
        char* dB = smem + ST * ASZ + buf * BSZ;
        #pragma unroll
        for (int s = tid; s < BM * 4; s += 256) {
            int row = s >> 2, seg = s & 3;
            cpa16(dA + row * 80 + seg * 16,
                  A + (long)(m0 + row) * lda + k0 + seg * 8);
        }
        #pragma unroll
        for (int s = tid; s < BN * 4; s += 256) {
            int row = s >> 2, seg = s & 3;
            cpa16(dB + row * 80 + seg * 16,
                  B + (long)(n0 + row) * ldb + k0 + seg * 8);
        }
    };

    #pragma unroll
    for (int s = 0; s < ST - 1; s++) {
        if (s < iters) load_stage(s, s);
        cp_commit();
    }

    for (int it = 0; it < iters; ++it) {
        cp_wait<ST - 2>();
        __syncthreads();

        if (it + ST - 1 < iters) load_stage(it + ST - 1, (it + ST - 1) % ST);
        cp_commit();

        const int buf = it % ST;
        const uint32_t aBase = smem_u + buf * ASZ;
        const uint32_t bBase = smem_u + ST * ASZ + buf * BSZ;

        #pragma unroll
        for (int ks = 0; ks < BK; ks += 16) {
            unsigned a[MT][4], b[NTL/2][4];
            #pragma unroll
            for (int mt = 0; mt < MT; mt++)
                ldm4(a[mt], aBase + aoff[mt] + ks * 2);
            #pragma unroll
            for (int p = 0; p < NTL/2; p++)
                ldm4(b[p], bBase + boff[p] + ks * 2);
            #pragma unroll
            for (int mt = 0; mt < MT; mt++)
                #pragma unroll
                for (int p = 0; p < NTL/2; p++) {
                    mma16(c[mt][2*p],   a[mt], &b[p][0]);
                    mma16(c[mt][2*p+1], a[mt], &b[p][2]);
                }
        }
    }

    // ---- epilogue ----
    auto ep = [&](float v, int n, long m) -> float {
        if constexpr (MODE == 0) {
            v += (bias2 && n >= 1024) ? bias2[n - 1024] : bias[n];
        } else if constexpr (MODE == 1) {
            v += bias[n] + res[m * ldres + n];
            v = (v - bnm[n]) * rsqrtf(bnv[n] + 1e-5f) * bng[n] + bnb[n];
        } else if constexpr (MODE == 2) {
            v += bias[n];
            v = 0.5f * v * (1.0f + erff(v * 0.70710678118654752f));
            v = (v - bnm[n]) * rsqrtf(bnv[n] + 1e-5f) * bng[n] + bnb[n];
        } else if constexpr (MODE == 3) {
            v = (mask[(long)zb * maskS1 + n] == 0) ? -1e9f : v * 0.125f;
        }
        return v;
    };

    const long cofs = (long)zb * cS1 + (long)zh * cS2;
    #pragma unroll
    for (int mt = 0; mt < MT; mt++) {
        #pragma unroll
        for (int nt = 0; nt < NTL; nt++) {
            const int row = m0 + wm * WM + mt * 16 + g;
            const int col = n0 + wn * WN + nt * 8 + 2 * t;
            float v00 = ep(c[mt][nt][0], col,     row);
            float v01 = ep(c[mt][nt][1], col + 1, row);
            float v10 = ep(c[mt][nt][2], col,     row + 8);
            float v11 = ep(c[mt][nt][3], col + 1, row + 8);
            if constexpr (OUTH) {
                __half* Ch = (__half*)Cv + cofs;
                *(__half2*)(Ch + (long)(row    ) * ldc + col) = __floats2half2_rn(v00, v01);
                *(__half2*)(Ch + (long)(row + 8) * ldc + col) = __floats2half2_rn(v10, v11);
            } else {
                float* Cf = (float*)Cv + cofs;
                *(float2*)(Cf + (long)(row    ) * ldc + col) = make_float2(v00, v01);
                *(float2*)(Cf + (long)(row + 8) * ldc + col) = make_float2(v10, v11);
            }
        }
    }
}

// ---------------- float -> half convert (vectorized) -------------------------
__global__ void __launch_bounds__(256)
cvt_k(const float* __restrict__ in, __half* __restrict__ out, int n4)
{
    int i = blockIdx.x * 256 + threadIdx.x;
    if (i < n4) {
        float4 v = ((const float4*)in)[i];
        ((__half2*)out)[2*i]   = __floats2half2_rn(v.x, v.y);
        ((__half2*)out)[2*i+1] = __floats2half2_rn(v.z, v.w);
    }
}

// ---------------- V transpose: kv[token][1024+h*64+dk] -> vt[b,h][dk][s] -----
__global__ void __launch_bounds__(256)
vt_k(const __half* __restrict__ v, int ldv, __half* __restrict__ vt)
{
    __shared__ __half tile[64][72];
    const int z = blockIdx.z;           // b*16+h
    const int b = z >> 4, h = z & 15;
    const int s0 = blockIdx.x * 64;
    const int tid = threadIdx.x;

    #pragma unroll
    for (int p = 0; p < 2; p++) {
        int r   = p * 32 + (tid >> 3);
        int seg = tid & 7;
        uint4 d = *(const uint4*)(v + ((long)(b * SS + s0 + r)) * ldv + h * 64 + seg * 8);
        *(uint4*)&tile[r][seg * 8] = d;
    }
    __syncthreads();
    #pragma unroll
    for (int p = 0; p < 2; p++) {
        int c   = p * 32 + (tid >> 3);
        int seg = tid & 7;
        __half tmp[8];
        #pragma unroll
        for (int j = 0; j < 8; j++) tmp[j] = tile[seg * 8 + j][c];
        *(uint4*)(vt + ((long)z * 64 + c) * SS + s0 + seg * 8) = *(uint4*)tmp;
    }
}

// ---------------- LayerNorm over D=1024; half output -------------------------
__global__ void __launch_bounds__(256)
ln_k(const float* __restrict__ x, const float* __restrict__ g,
     const float* __restrict__ b, __half* __restrict__ o)
{
    __shared__ float red[8];
    const long row = blockIdx.x;
    const int  t = threadIdx.x, lane = t & 31, w = t >> 5;

    float4 v = ((const float4*)(x + row * DD))[t];
    float s = v.x + v.y + v.z + v.w;
    #pragma unroll
    for (int off = 16; off; off >>= 1) s += __shfl_down_sync(0xffffffffu, s, off);
    if (!lane) red[w] = s;
    __syncthreads();
    if (t == 0) { float a = 0.f; for (int i = 0; i < 8; i++) a += red[i]; red[0] = a; }
    __syncthreads();
    const float mu = red[0] * (1.0f / DD);
    __syncthreads();

    float d0 = v.x - mu, d1 = v.y - mu, d2 = v.z - mu, d3 = v.w - mu;
    float sq = d0*d0 + d1*d1 + d2*d2 + d3*d3;
    #pragma unroll
    for (int off = 16; off; off >>= 1) sq += __shfl_down_sync(0xffffffffu, sq, off);
    if (!lane) red[w] = sq;
    __syncthreads();
    if (t == 0) { float a = 0.f; for (int i = 0; i < 8; i++) a += red[i]; red[0] = a; }
    __syncthreads();
    const float rs = rsqrtf(red[0] * (1.0f / DD) + 1e-5f);

    float4 g4 = ((const float4*)g)[t];
    float4 b4 = ((const float4*)b)[t];
    __half2* op = (__half2*)(o + row * DD);
    op[2*t]   = __floats2half2_rn(d0 * rs * g4.x + b4.x, d1 * rs * g4.y + b4.y);
    op[2*t+1] = __floats2half2_rn(d2 * rs * g4.z + b4.z, d3 * rs * g4.w + b4.w);
}

// ---------------- row softmax over S=1024; fp32 in-place + half copy ---------
__global__ void __launch_bounds__(256)
softmax_k(float* __restrict__ a, __half* __restrict__ ah)
{
    __shared__ float red[8];
    const long row = blockIdx.x;
    const int  t = threadIdx.x, lane = t & 31, w = t >> 5;

    float4* p = (float4*)(a + row * (long)SS);
    float4 v = p[t];
    float mx = fmaxf(fmaxf(v.x, v.y), fmaxf(v.z, v.w));
    #pragma unroll
    for (int off = 16; off; off >>= 1)
        mx = fmaxf(mx, __shfl_down_sync(0xffffffffu, mx, off));
    if (!lane) red[w] = mx;
    __syncthreads();
    if (t == 0) { float m = red[0]; for (int i = 1; i < 8; i++) m = fmaxf(m, red[i]); red[0] = m; }
    __syncthreads();
    const float rmax = red[0];
    __syncthreads();

    float e0 = __expf(v.x - rmax), e1 = __expf(v.y - rmax);
    float e2 = __expf(v.z - rmax), e3 = __expf(v.w - rmax);
    float s = e0 + e1 + e2 + e3;
    #pragma unroll
    for (int off = 16; off; off >>= 1) s += __shfl_down_sync(0xffffffffu, s, off);
    if (!lane) red[w] = s;
    __syncthreads();
    if (t == 0) { float a2 = 0.f; for (int i = 0; i < 8; i++) a2 += red[i]; red[0] = a2; }
    __syncthreads();
    const float inv = 1.0f / red[0];

    float r0 = e0 * inv, r1 = e1 * inv, r2 = e2 * inv, r3 = e3 * inv;
    p[t] = make_float4(r0, r1, r2, r3);
    __half2* hp = (__half2*)(ah + row * (long)SS);
    hp[2*t]   = __floats2half2_rn(r0, r1);
    hp[2*t+1] = __floats2half2_rn(r2, r3);
}

// ---------------- host orchestration ----------------------------------------
extern "C" void kernel_launch(void* const* d_in, const int* in_sizes, int n_in,
                              void* d_out, int out_size)
{
    const float* x    = (const float*)d_in[0];
    const int*   mask = (const int*)  d_in[1];
    const float* Wq = (const float*)d_in[2];  const float* bq = (const float*)d_in[3];
    const float* Wk = (const float*)d_in[4];  const float* bk = (const float*)d_in[5];
    const float* Wv = (const float*)d_in[6];  const float* bv = (const float*)d_in[7];
    const float* Wo = (const float*)d_in[8];  const float* bo = (const float*)d_in[9];
    const float* lag = (const float*)d_in[10]; const float* lab = (const float*)d_in[11];
    const float* W1 = (const float*)d_in[12]; const float* b1 = (const float*)d_in[13];
    const float* W2 = (const float*)d_in[14]; const float* b2 = (const float*)d_in[15];
    const float* lfg = (const float*)d_in[16]; const float* lfb = (const float*)d_in[17];
    const float* bnffg = (const float*)d_in[18]; const float* bnffb = (const float*)d_in[19];
    const float* bnffm = (const float*)d_in[20]; const float* bnffv = (const float*)d_in[21];
    const float* bn1g = (const float*)d_in[22]; const float* bn1b = (const float*)d_in[23];
    const float* bn1m = (const float*)d_in[24]; const float* bn1v = (const float*)d_in[25];
    const float* bn2g = (const float*)d_in[26]; const float* bn2b = (const float*)d_in[27];
    const float* bn2m = (const float*)d_in[28]; const float* bn2v = (const float*)d_in[29];

    __half *xq, *xr, *q, *kv, *vt, *ctx, *h, *w, *ah;
    float *x1;
    cudaGetSymbolAddress((void**)&xq,  g_xq);
    cudaGetSymbolAddress((void**)&xr,  g_xr);
    cudaGetSymbolAddress((void**)&q,   g_q);
    cudaGetSymbolAddress((void**)&kv,  g_kv);
    cudaGetSymbolAddress((void**)&vt,  g_vt);
    cudaGetSymbolAddress((void**)&ctx, g_ctx);
    cudaGetSymbolAddress((void**)&x1,  g_x1);
    cudaGetSymbolAddress((void**)&h,   g_h);
    cudaGetSymbolAddress((void**)&w,   g_w);
    cudaGetSymbolAddress((void**)&ah,  g_ah);

    __half* cWq = w;
    __half* cWk = w + 1*1024*1024;     // cWk..cWv contiguous = fused KV weight [2048,1024]
    __half* cWv = w + 2*1024*1024;
    __half* cWo = w + 3*1024*1024;
    __half* cW1 = w + 4*1024*1024;
    __half* cW2 = w + 8*1024*1024;

    float* outx = (float*)d_out;                    // [B,S,D]
    float* outa = outx + (long)NTOK * DD;           // [B,H,S,S]

    constexpr int SM_B  = 4 * (128*80 + 256*80);    // 122880 B (big NT GEMMs)
    constexpr int SM_S  = 3 * (128*80 + 128*80);    // 61440 B (scores)
    constexpr int SM_AV = 3 * (128*80 +  64*80);    // 46080 B (attn@V)

    //                 BM  BN  WM WN ST  MODE OUTH
    auto* kP  = gemm_h<128,256,64,64,4,  0,   true >;  // q / kv -> half
    auto* kS  = gemm_h<128,128,64,32,3,  3,   false>;  // scores -> fp32
    auto* kAV = gemm_h<128, 64,32,32,3,  4,   true >;  // attn_h @ Vt -> ctx half
    auto* kR  = gemm_h<128,256,64,64,4,  1,   false>;  // O-proj / W2 -> fp32
    auto* kG  = gemm_h<128,256,64,64,4,  2,   true >;  // W1 -> h half
    cudaFuncSetAttribute((const void*)kP,  cudaFuncAttributeMaxDynamicSharedMemorySize, SM_B);
    cudaFuncSetAttribute((const void*)kS,  cudaFuncAttributeMaxDynamicSharedMemorySize, SM_S);
    cudaFuncSetAttribute((const void*)kAV, cudaFuncAttributeMaxDynamicSharedMemorySize, SM_AV);
    cudaFuncSetAttribute((const void*)kR,  cudaFuncAttributeMaxDynamicSharedMemorySize, SM_B);
    cudaFuncSetAttribute((const void*)kG,  cudaFuncAttributeMaxDynamicSharedMemorySize, SM_B);

    // 0) convert weights + x to half
    cvt_k<<<(1024*1024/4 + 255)/256, 256>>>(Wq, cWq, 1024*1024/4);
    cvt_k<<<(1024*1024/4 + 255)/256, 256>>>(Wk, cWk, 1024*1024/4);
    cvt_k<<<(1024*1024/4 + 255)/256, 256>>>(Wv, cWv, 1024*1024/4);
    cvt_k<<<(1024*1024/4 + 255)/256, 256>>>(Wo, cWo, 1024*1024/4);
    cvt_k<<<(4*1024*1024/4 + 255)/256, 256>>>(W1, cW1, 4*1024*1024/4);
    cvt_k<<<(4*1024*1024/4 + 255)/256, 256>>>(W2, cW2, 4*1024*1024/4);
    cvt_k<<<(NTOK*DD/4 + 255)/256, 256>>>(x, xr, NTOK*DD/4);

    // 1) pre-LN for query path (half out)
    ln_k<<<NTOK, 256>>>(x, lag, lab, xq);

    // 2) q projection (N=1024) + fused kv projection (N=2048)
    dim3 gQ(DD / 256, NTOK / 128, 1);
    kP<<<gQ, 256, SM_B>>>(xq, DD,0,0, cWq, DD,0,0, q, DD,0,0, DD,
        bq, nullptr, nullptr,0, nullptr,nullptr,nullptr,nullptr, nullptr,0);
    dim3 gKV(2048 / 256, NTOK / 128, 1);
    kP<<<gKV, 256, SM_B>>>(xr, DD,0,0, cWk, DD,0,0, kv, 2048,0,0, DD,
        bk, bv, nullptr,0, nullptr,nullptr,nullptr,nullptr, nullptr,0);

    // 2b) transpose V part of kv: [s, dk] -> [dk, s] per (b,h)
    dim3 gV(SS / 64, 1, BB * HH);
    vt_k<<<gV, 256>>>(kv + 1024, 2048, vt);

    // 3) scores = Q K^T / 8 (+mask) into d_out attn region (K part of kv)
    dim3 gS(SS / 128, SS / 128, BB * HH);
    kS<<<gS, 256, SM_S>>>(
        q,  DD,   (long)SS * DD,   64,
        kv, 2048, (long)SS * 2048, 64,
        outa, SS, (long)HH * SS * SS, (long)SS * SS,
        DKK, nullptr, nullptr, nullptr,0, nullptr,nullptr,nullptr,nullptr, mask, SS);

    // 4) softmax in place (fp32 attn output) + half copy for AV
    softmax_k<<<BB * HH * SS, 256>>>(outa, ah);

    // 5) context = attn_h @ Vt  (all-half NT GEMM)
    dim3 gC(1, SS / 128, BB * HH);
    kAV<<<gC, 256, SM_AV>>>(
        ah,   SS, (long)HH * SS * SS, (long)SS * SS,
        vt,   SS, (long)HH * DKK * SS, (long)DKK * SS,
        ctx,  DD, (long)SS * DD, 64,
        SS, nullptr, nullptr, nullptr,0, nullptr,nullptr,nullptr,nullptr, nullptr,0);

    // 6) O projection + residual(x) + bn1 -> x1 (fp32)
    dim3 gO(DD / 256, NTOK / 128, 1);
    kR<<<gO, 256, SM_B>>>(ctx, DD,0,0, cWo, DD,0,0, x1, DD,0,0, DD,
        bo, nullptr, x, DD, bn1g,bn1b,bn1m,bn1v, nullptr,0);

    // 7) FFN pre-LN (half out)
    ln_k<<<NTOK, 256>>>(x1, lfg, lfb, xq);

    // 8) h = bnff(gelu(xn W1^T + b1)) -> half  M=8192 N=4096 K=1024
    dim3 g1(DF / 256, NTOK / 128, 1);
    kG<<<g1, 256, SM_B>>>(xq, DD,0,0, cW1, DD,0,0, h, DF,0,0, DD,
        b1, nullptr, nullptr,0, bnffg,bnffb,bnffm,bnffv, nullptr,0);

    // 9) out_x = bn2(h W2^T + b2 + x1)  M=8192 N=1024 K=4096
    dim3 g2(DD / 256, NTOK / 128, 1);
    kR<<<g2, 256, SM_B>>>(h, DF,0,0, cW2, DF,0,0, outx, DD,0,0, DF,
        b2, nullptr, x1, DD, bn2g,bn2b,bn2m,bn2v, nullptr,0);
}